// round 4
// baseline (speedup 1.0000x reference)
#include <cuda_runtime.h>
#include <cstdint>

#define E_DIM 1024
#define H_DIM 16
#define T_DIM 1024
#define B_DIM 4
#define D_DIM 64
#define RANKV 4

// ---------------- scratch (device globals; no allocation allowed) ----------
__device__ float g_win [(size_t)E_DIM * 3 * E_DIM];
__device__ float g_wpos[(size_t)E_DIM * E_DIM];
__device__ float g_wout[(size_t)E_DIM * E_DIM];
__device__ float g_qkv [(size_t)T_DIM * B_DIM * 3 * E_DIM];
__device__ float g_qw  [(size_t)B_DIM * H_DIM * T_DIM * D_DIM];
__device__ float g_qr  [(size_t)B_DIM * H_DIM * T_DIM * D_DIM];
__device__ float g_k   [(size_t)B_DIM * H_DIM * T_DIM * D_DIM];
__device__ float g_v   [(size_t)B_DIM * H_DIM * T_DIM * D_DIM];
__device__ float g_rktmp[(size_t)T_DIM * E_DIM];
__device__ float g_rk  [(size_t)H_DIM * T_DIM * D_DIM];
__device__ float g_scores[(size_t)B_DIM * H_DIM * T_DIM * T_DIM];   // 268 MB
__device__ float g_ctx [(size_t)T_DIM * B_DIM * E_DIM];

// ---------------- W + sum_r outer(r,s) --------------------------------------
__global__ void build_w_kernel(const float* __restrict__ base,
                               const float* __restrict__ r,
                               const float* __restrict__ s,
                               const int* __restrict__ idx,
                               float* __restrict__ out, int F)
{
    int lang = idx[0];
    long i = (long)blockIdx.x * blockDim.x + threadIdx.x;
    long total = (long)E_DIM * F;
    if (i >= total) return;
    int e = (int)(i / F);
    int f = (int)(i % F);
    const float* rl = r + (long)lang * RANKV * E_DIM;
    const float* sl = s + (long)lang * RANKV * F;
    float v = base[i];
#pragma unroll
    for (int q = 0; q < RANKV; ++q)
        v += rl[q * E_DIM + e] * sl[(long)q * F + f];
    out[i] = v;
}

// ============================================================================
// Templated double-buffered SIMT GEMM. BKC=16 k-slice, 256 threads.
//   NN: C[M,N] = A[M,K] @ B[K,N] (+bias)
//   NT: C[M,N] = A[M,K] @ B[N,K]^T, EPI=0 plain store, EPI=1 rel-shift +=
// Requires: M % TBM == 0, N % TBN == 0, K % 16 == 0,
//           (TBM/TM)*(TBN/TN) == 256, TM,TN multiples of 4, TBM,TBN mult of 64.
// ============================================================================
#define BKC 16

template<int TBM, int TBN, int TM, int TN>
__global__ __launch_bounds__(256)
void gemm_nn_t(const float* __restrict__ A, const float* __restrict__ B,
               const float* __restrict__ bias, float* __restrict__ C,
               int K, int lda, int ldb, int ldc,
               long sAz, long sBz, long sCz)
{
    __shared__ __align__(16) float As[2][BKC][TBM];
    __shared__ __align__(16) float Bs[2][BKC][TBN];
    int z = blockIdx.z;
    A += (long)z * sAz;  B += (long)z * sBz;  C += (long)z * sCz;
    int m0 = blockIdx.y * TBM, n0 = blockIdx.x * TBN;
    int tid = threadIdx.x;
    constexpr int TX = TBN / TN;
    int tx = tid % TX, ty = tid / TX;

    // A loader: (row, 4 k-cols) per thread, 64 rows per pass
    int ar = tid >> 2, akc = (tid & 3) * 4;
    constexpr int AIT = TBM / 64;
    // B loader: (k-row, 4 n-cols) per thread
    constexpr int BN4 = TBN / 4;
    int bn = (tid % BN4) * 4, bkr = tid / BN4;
    constexpr int BKSTEP = 256 / BN4;
    constexpr int BIT = BKC / BKSTEP;

    float acc[TM][TN] = {};
    float4 ra[AIT], rb[BIT];

    // tile 0 -> buf 0
#pragma unroll
    for (int i = 0; i < AIT; ++i) {
        float4 v = *(const float4*)&A[(long)(m0 + ar + i * 64) * lda + akc];
        int rr = ar + i * 64;
        As[0][akc+0][rr]=v.x; As[0][akc+1][rr]=v.y; As[0][akc+2][rr]=v.z; As[0][akc+3][rr]=v.w;
    }
#pragma unroll
    for (int i = 0; i < BIT; ++i)
        *(float4*)&Bs[0][bkr + i * BKSTEP][bn] =
            *(const float4*)&B[(long)(bkr + i * BKSTEP) * ldb + n0 + bn];
    __syncthreads();

    int KT = K / BKC;
    for (int kt = 0; kt < KT; ++kt) {
        int cur = kt & 1;
        if (kt + 1 < KT) {
            int k0 = (kt + 1) * BKC;
#pragma unroll
            for (int i = 0; i < AIT; ++i)
                ra[i] = *(const float4*)&A[(long)(m0 + ar + i * 64) * lda + k0 + akc];
#pragma unroll
            for (int i = 0; i < BIT; ++i)
                rb[i] = *(const float4*)&B[(long)(k0 + bkr + i * BKSTEP) * ldb + n0 + bn];
        }
#pragma unroll
        for (int k = 0; k < BKC; ++k) {
            float a[TM], b[TN];
#pragma unroll
            for (int i = 0; i < TM; i += 4) *(float4*)&a[i] = *(const float4*)&As[cur][k][ty * TM + i];
#pragma unroll
            for (int j = 0; j < TN; j += 4) *(float4*)&b[j] = *(const float4*)&Bs[cur][k][tx * TN + j];
#pragma unroll
            for (int i = 0; i < TM; ++i)
#pragma unroll
                for (int j = 0; j < TN; ++j)
                    acc[i][j] += a[i] * b[j];
        }
        if (kt + 1 < KT) {
            int nxt = cur ^ 1;
#pragma unroll
            for (int i = 0; i < AIT; ++i) {
                int rr = ar + i * 64;
                As[nxt][akc+0][rr]=ra[i].x; As[nxt][akc+1][rr]=ra[i].y;
                As[nxt][akc+2][rr]=ra[i].z; As[nxt][akc+3][rr]=ra[i].w;
            }
#pragma unroll
            for (int i = 0; i < BIT; ++i)
                *(float4*)&Bs[nxt][bkr + i * BKSTEP][bn] = rb[i];
        }
        __syncthreads();
    }

#pragma unroll
    for (int i = 0; i < TM; ++i) {
        int m = m0 + ty * TM + i;
#pragma unroll
        for (int j = 0; j < TN; j += 4) {
            int n = n0 + tx * TN + j;
            float4 v = {acc[i][j], acc[i][j+1], acc[i][j+2], acc[i][j+3]};
            if (bias) { v.x += bias[n]; v.y += bias[n+1]; v.z += bias[n+2]; v.w += bias[n+3]; }
            *(float4*)&C[(long)m * ldc + n] = v;
        }
    }
}

// NT: B is [N,K] row-major; loaded transposed like A.
// EPI=0: plain store. EPI=1: Transformer-XL rel-shift scatter-add of raw
// bd element (m, n):
//   n >= T-1-m          -> C[m,   n+m-(T-1)] += v   (lower tri + diag, j<=i)
//   n <  T-1-m && m>=1  -> C[m-1, n+m+1]     += v   (upper tri wrap, j>=i+2)
//   (C[i][i+1] gets nothing: zero pad; raw row0 early cols dropped)
// Branch targets are disjoint and each map is injective -> bijection ->
// non-atomic += race-free.
template<int TBM, int TBN, int TM, int TN, int EPI>
__global__ __launch_bounds__(256)
void gemm_nt_t(const float* __restrict__ A, const float* __restrict__ B,
               float* __restrict__ C,
               int K, int lda, int ldb, int ldc,
               long sAz, long sBz, long sCz, int bmod)
{
    __shared__ __align__(16) float As[2][BKC][TBM];
    __shared__ __align__(16) float Bs[2][BKC][TBN];
    int z = blockIdx.z;
    int zb = bmod ? (z % bmod) : z;
    A += (long)z * sAz;  B += (long)zb * sBz;  C += (long)z * sCz;
    int m0 = blockIdx.y * TBM, n0 = blockIdx.x * TBN;
    int tid = threadIdx.x;
    constexpr int TX = TBN / TN;
    int tx = tid % TX, ty = tid / TX;

    int lr = tid >> 2, lkc = (tid & 3) * 4;
    constexpr int AIT = TBM / 64;
    constexpr int BIT = TBN / 64;

    float acc[TM][TN] = {};
    float4 ra[AIT], rb[BIT];

#pragma unroll
    for (int i = 0; i < AIT; ++i) {
        float4 v = *(const float4*)&A[(long)(m0 + lr + i * 64) * lda + lkc];
        int rr = lr + i * 64;
        As[0][lkc+0][rr]=v.x; As[0][lkc+1][rr]=v.y; As[0][lkc+2][rr]=v.z; As[0][lkc+3][rr]=v.w;
    }
#pragma unroll
    for (int i = 0; i < BIT; ++i) {
        float4 v = *(const float4*)&B[(long)(n0 + lr + i * 64) * ldb + lkc];
        int rr = lr + i * 64;
        Bs[0][lkc+0][rr]=v.x; Bs[0][lkc+1][rr]=v.y; Bs[0][lkc+2][rr]=v.z; Bs[0][lkc+3][rr]=v.w;
    }
    __syncthreads();

    int KT = K / BKC;
    for (int kt = 0; kt < KT; ++kt) {
        int cur = kt & 1;
        if (kt + 1 < KT) {
            int k0 = (kt + 1) * BKC;
#pragma unroll
            for (int i = 0; i < AIT; ++i)
                ra[i] = *(const float4*)&A[(long)(m0 + lr + i * 64) * lda + k0 + lkc];
#pragma unroll
            for (int i = 0; i < BIT; ++i)
                rb[i] = *(const float4*)&B[(long)(n0 + lr + i * 64) * ldb + k0 + lkc];
        }
#pragma unroll
        for (int k = 0; k < BKC; ++k) {
            float a[TM], b[TN];
#pragma unroll
            for (int i = 0; i < TM; i += 4) *(float4*)&a[i] = *(const float4*)&As[cur][k][ty * TM + i];
#pragma unroll
            for (int j = 0; j < TN; j += 4) *(float4*)&b[j] = *(const float4*)&Bs[cur][k][tx * TN + j];
#pragma unroll
            for (int i = 0; i < TM; ++i)
#pragma unroll
                for (int j = 0; j < TN; ++j)
                    acc[i][j] += a[i] * b[j];
        }
        if (kt + 1 < KT) {
            int nxt = cur ^ 1;
#pragma unroll
            for (int i = 0; i < AIT; ++i) {
                int rr = lr + i * 64;
                As[nxt][lkc+0][rr]=ra[i].x; As[nxt][lkc+1][rr]=ra[i].y;
                As[nxt][lkc+2][rr]=ra[i].z; As[nxt][lkc+3][rr]=ra[i].w;
            }
#pragma unroll
            for (int i = 0; i < BIT; ++i) {
                int rr = lr + i * 64;
                Bs[nxt][lkc+0][rr]=rb[i].x; Bs[nxt][lkc+1][rr]=rb[i].y;
                Bs[nxt][lkc+2][rr]=rb[i].z; Bs[nxt][lkc+3][rr]=rb[i].w;
            }
        }
        __syncthreads();
    }

#pragma unroll
    for (int i = 0; i < TM; ++i) {
        int m = m0 + ty * TM + i;
#pragma unroll
        for (int j = 0; j < TN; ++j) {
            int n = n0 + tx * TN + j;
            if (EPI == 0) {
                C[(long)m * ldc + n] = acc[i][j];
            } else {
                int jj = n + m - (T_DIM - 1);
                if (jj >= 0)
                    C[(long)m * ldc + jj] += acc[i][j];
                else if (m >= 1)
                    C[(long)(m - 1) * ldc + (n + m + 1)] += acc[i][j];
            }
        }
    }
}

// ---------------- scatter qkv -> head-major q_w/q_r/k/v ---------------------
__global__ void scatter_qkv_kernel(const float* __restrict__ qkv,
                                   const float* __restrict__ rwb,
                                   const float* __restrict__ rrb,
                                   float* __restrict__ qw, float* __restrict__ qr,
                                   float* __restrict__ karr, float* __restrict__ varr)
{
    long i = (long)blockIdx.x * blockDim.x + threadIdx.x;
    int row = (int)(i / (3 * E_DIM));
    int col = (int)(i % (3 * E_DIM));
    int t = row >> 2, b = row & 3;         // B_DIM = 4
    int sec = col >> 10, f = col & (E_DIM - 1);
    int h = f >> 6, d = f & 63;
    long dst = (((long)(b * H_DIM + h) * T_DIM + t) << 6) + d;
    float v = qkv[i];
    if (sec == 0) { qw[dst] = v + rwb[f]; qr[dst] = v + rrb[f]; }
    else if (sec == 1) karr[dst] = v;
    else               varr[dst] = v;
}

// ---------------- scatter rk_tmp[T,E] -> rk[H,T,D] --------------------------
__global__ void scatter_rk_kernel(const float* __restrict__ tmp, float* __restrict__ rk)
{
    long i = (long)blockIdx.x * blockDim.x + threadIdx.x;
    int j = (int)(i >> 10), f = (int)(i & (E_DIM - 1));
    int h = f >> 6, d = f & 63;
    rk[(((long)h * T_DIM + j) << 6) + d] = tmp[i];
}

// ---------------- rowwise softmax (scale + mask fused, shuffle reduce) ------
__global__ __launch_bounds__(256)
void softmax_kernel(float* __restrict__ scores, const unsigned char* __restrict__ mask)
{
    int row = blockIdx.x;                  // [B*H*T)
    int b = row >> 14;                     // / (H*T)
    float* p = scores + (long)row * T_DIM;
    int t = threadIdx.x;
    int lane = t & 31, wid = t >> 5;
    float4 v = ((const float4*)p)[t];
    float x[4] = {v.x, v.y, v.z, v.w};
    const unsigned char* mb = mask + (long)b * T_DIM + t * 4;
    const float scale = 0.125f;            // 1/sqrt(64)
#pragma unroll
    for (int c = 0; c < 4; ++c) {
        x[c] *= scale;
        if (mb[c]) x[c] = -1e9f;
    }
    __shared__ float wred[8];
    // ---- max ----
    float mx = fmaxf(fmaxf(x[0], x[1]), fmaxf(x[2], x[3]));
#pragma unroll
    for (int off = 16; off > 0; off >>= 1)
        mx = fmaxf(mx, __shfl_xor_sync(0xFFFFFFFFu, mx, off));
    if (lane == 0) wred[wid] = mx;
    __syncthreads();
    float m0 = wred[0];
#pragma unroll
    for (int w = 1; w < 8; ++w) m0 = fmaxf(m0, wred[w]);
    // ---- exp + sum ----
    float sum = 0.f;
#pragma unroll
    for (int c = 0; c < 4; ++c) { x[c] = __expf(x[c] - m0); sum += x[c]; }
#pragma unroll
    for (int off = 16; off > 0; off >>= 1)
        sum += __shfl_xor_sync(0xFFFFFFFFu, sum, off);
    __syncthreads();                        // wred reuse hazard
    if (lane == 0) wred[wid] = sum;
    __syncthreads();
    float s0 = wred[0];
#pragma unroll
    for (int w = 1; w < 8; ++w) s0 += wred[w];
    float inv = 1.0f / s0;
    float4 o = {x[0] * inv, x[1] * inv, x[2] * inv, x[3] * inv};
    ((float4*)p)[t] = o;
}

// ---------------------------------------------------------------------------
extern "C" void kernel_launch(void* const* d_in, const int* in_sizes, int n_in,
                              void* d_out, int out_size)
{
    const float* input  = (const float*)d_in[0];   // [T,B,E]
    const float* pos    = (const float*)d_in[1];   // [T,1,E]
    const int*   indices= (const int*)d_in[2];
    const unsigned char* mask = (const unsigned char*)d_in[3]; // [B,T] bool
    const float* w_in_b = (const float*)d_in[4];
    const float* w_pos_b= (const float*)d_in[5];
    const float* w_out_b= (const float*)d_in[6];
    const float* b_in   = (const float*)d_in[7];
    const float* b_pos  = (const float*)d_in[8];
    const float* b_out  = (const float*)d_in[9];
    const float* r_i = (const float*)d_in[10];
    const float* s_i = (const float*)d_in[11];
    const float* r_p = (const float*)d_in[12];
    const float* s_p = (const float*)d_in[13];
    const float* r_o = (const float*)d_in[14];
    const float* s_o = (const float*)d_in[15];
    const float* r_w_bias = (const float*)d_in[16];
    const float* r_r_bias = (const float*)d_in[17];
    float* out = (float*)d_out;

    float *win, *wpos, *wout, *qkv, *qw, *qr, *karr, *varr, *rktmp, *rk, *scores, *ctx;
    cudaGetSymbolAddress((void**)&win,  g_win);
    cudaGetSymbolAddress((void**)&wpos, g_wpos);
    cudaGetSymbolAddress((void**)&wout, g_wout);
    cudaGetSymbolAddress((void**)&qkv,  g_qkv);
    cudaGetSymbolAddress((void**)&qw,   g_qw);
    cudaGetSymbolAddress((void**)&qr,   g_qr);
    cudaGetSymbolAddress((void**)&karr, g_k);
    cudaGetSymbolAddress((void**)&varr, g_v);
    cudaGetSymbolAddress((void**)&rktmp,g_rktmp);
    cudaGetSymbolAddress((void**)&rk,   g_rk);
    cudaGetSymbolAddress((void**)&scores, g_scores);
    cudaGetSymbolAddress((void**)&ctx,  g_ctx);

    const int TB = T_DIM * B_DIM;          // 4096
    const int ZBH = B_DIM * H_DIM;         // 64

    // 1) multilingual low-rank weight materialization
    build_w_kernel<<<(E_DIM * 3 * E_DIM) / 256, 256>>>(w_in_b,  r_i, s_i, indices, win,  3 * E_DIM);
    build_w_kernel<<<(E_DIM * E_DIM)     / 256, 256>>>(w_pos_b, r_p, s_p, indices, wpos, E_DIM);
    build_w_kernel<<<(E_DIM * E_DIM)     / 256, 256>>>(w_out_b, r_o, s_o, indices, wout, E_DIM);

    // 2) qkv = input @ w_in + b_in   [4096,1024]x[1024,3072]
    gemm_nn_t<128,128,8,8><<<dim3(3 * E_DIM / 128, TB / 128, 1), 256>>>(
        input, win, b_in, qkv, E_DIM, E_DIM, 3 * E_DIM, 3 * E_DIM, 0, 0, 0);

    // 3) scatter to [B,H,T,D]; q gets r_w_bias / r_r_bias variants
    scatter_qkv_kernel<<<(long)TB * 3 * E_DIM / 256, 256>>>(qkv, r_w_bias, r_r_bias, qw, qr, karr, varr);

    // 4) r_head_k = pos @ w_pos + b_pos   [1024,1024]x[1024,1024]
    gemm_nn_t<128,128,8,8><<<dim3(E_DIM / 128, T_DIM / 128, 1), 256>>>(
        pos, wpos, b_pos, rktmp, E_DIM, E_DIM, E_DIM, E_DIM, 0, 0, 0);
    scatter_rk_kernel<<<(long)T_DIM * E_DIM / 256, 256>>>(rktmp, rk);

    // 5) ac scores: per (b,h)  q_w @ k^T  -> scores
    gemm_nt_t<128,128,8,8,0><<<dim3(T_DIM / 128, T_DIM / 128, ZBH), 256>>>(
        qw, karr, scores, D_DIM, D_DIM, D_DIM, T_DIM,
        (long)T_DIM * D_DIM, (long)T_DIM * D_DIM, (long)T_DIM * T_DIM, 0);

    // 6) bd scores: per (b,h)  q_r @ rk[h]^T, rel-shift scatter-add into scores
    gemm_nt_t<128,128,8,8,1><<<dim3(T_DIM / 128, T_DIM / 128, ZBH), 256>>>(
        qr, rk, scores, D_DIM, D_DIM, D_DIM, T_DIM,
        (long)T_DIM * D_DIM, (long)T_DIM * D_DIM, (long)T_DIM * T_DIM, H_DIM);

    // 7) softmax over last dim (scale + key_padding_mask fused)
    softmax_kernel<<<ZBH * T_DIM, 256>>>(scores, mask);

    // 8) ctx = attn @ v  per (b,h): [T,T]x[T,D] -> ctx[T, B*E] interleaved
    gemm_nn_t<128,64,8,4><<<dim3(1, T_DIM / 128, ZBH), 256>>>(
        scores, varr, nullptr, ctx, T_DIM, T_DIM, D_DIM, B_DIM * E_DIM,
        (long)T_DIM * T_DIM, (long)T_DIM * D_DIM, (long)D_DIM);

    // 9) out = ctx @ w_out + b_out   [4096,1024]x[1024,1024]
    gemm_nn_t<128,128,8,8><<<dim3(E_DIM / 128, TB / 128, 1), 256>>>(
        ctx, wout, b_out, out, E_DIM, E_DIM, E_DIM, E_DIM, 0, 0, 0);
}

// round 13
// speedup vs baseline: 1.4597x; 1.4597x over previous
#include <cuda_runtime.h>
#include <cuda_bf16.h>
#include <cstdint>

#define E_DIM 1024
#define H_DIM 16
#define T_DIM 1024
#define B_DIM 4
#define D_DIM 64
#define RANKV 4

// ======================= helpers ============================================
__device__ __forceinline__ uint32_t smem_to_u32(const void* p) {
    uint32_t a;
    asm("{ .reg .u64 t; cvta.to.shared.u64 t, %1; cvt.u32.u64 %0, t; }" : "=r"(a) : "l"(p));
    return a;
}
__device__ __forceinline__ void bsplit(float v, __nv_bfloat16& h, __nv_bfloat16& l) {
    h = __float2bfloat16(v);
    l = __float2bfloat16(v - __bfloat162float(h));
}
// Ampere-class bf16 tensor-core MMA (legal at compute_103; no tcgen05 on this toolchain)
__device__ __forceinline__ void mma16816(float* c, const uint32_t* a, const uint32_t* b) {
    asm volatile(
        "mma.sync.aligned.m16n8k16.row.col.f32.bf16.bf16.f32 "
        "{%0,%1,%2,%3}, {%4,%5,%6,%7}, {%8,%9}, {%0,%1,%2,%3};\n"
        : "+f"(c[0]), "+f"(c[1]), "+f"(c[2]), "+f"(c[3])
        : "r"(a[0]), "r"(a[1]), "r"(a[2]), "r"(a[3]), "r"(b[0]), "r"(b[1]));
}
#define CP_ASYNC16(dst, src) \
    asm volatile("cp.async.cg.shared.global [%0], [%1], 16;" :: "r"(dst), "l"(src))
#define CP_COMMIT() asm volatile("cp.async.commit_group;" ::: "memory")
#define CP_WAIT1()  asm volatile("cp.async.wait_group 1;" ::: "memory")
#define CP_WAIT0()  asm volatile("cp.async.wait_group 0;" ::: "memory")

// ---------------- scratch (device globals; no allocation allowed) ----------
__device__ float g_qkv  [(size_t)4096 * 3072];
__device__ float g_rktmp[(size_t)T_DIM * E_DIM];
__device__ float g_scores[(size_t)64 * T_DIM * T_DIM];              // 268 MB
__device__ __nv_bfloat16 g_qwh[(size_t)64*T_DIM*64], g_qwl[(size_t)64*T_DIM*64];
__device__ __nv_bfloat16 g_qrh[(size_t)64*T_DIM*64], g_qrl[(size_t)64*T_DIM*64];
__device__ __nv_bfloat16 g_kh [(size_t)64*T_DIM*64], g_kl [(size_t)64*T_DIM*64];
__device__ __nv_bfloat16 g_vth[(size_t)64*64*T_DIM], g_vtl[(size_t)64*64*T_DIM]; // v^T [z][d][t]
__device__ __nv_bfloat16 g_rkh[(size_t)16*T_DIM*64], g_rkl[(size_t)16*T_DIM*64];
__device__ __nv_bfloat16 g_ath[(size_t)64*T_DIM*T_DIM], g_atl[(size_t)64*T_DIM*T_DIM]; // 268 MB
__device__ __nv_bfloat16 g_cxh[(size_t)4096*E_DIM], g_cxl[(size_t)4096*E_DIM];
__device__ __nv_bfloat16 g_wtih[(size_t)3072*E_DIM], g_wtil[(size_t)3072*E_DIM];
__device__ __nv_bfloat16 g_wtph[(size_t)E_DIM*E_DIM], g_wtpl[(size_t)E_DIM*E_DIM];
__device__ __nv_bfloat16 g_wtoh[(size_t)E_DIM*E_DIM], g_wtol[(size_t)E_DIM*E_DIM];
__device__ __nv_bfloat16 g_inh[(size_t)4096*E_DIM], g_inl[(size_t)4096*E_DIM];
__device__ __nv_bfloat16 g_psh[(size_t)T_DIM*E_DIM], g_psl[(size_t)T_DIM*E_DIM];

// ---- W^T build + low-rank + bf16 hi/lo split (tiled transpose) -------------
__global__ void build_wt_split(const float* __restrict__ base,
                               const float* __restrict__ r,
                               const float* __restrict__ s,
                               const int* __restrict__ idx,
                               __nv_bfloat16* __restrict__ oh,
                               __nv_bfloat16* __restrict__ ol, int N)
{
    __shared__ float tile[32][33];
    int lang = idx[0];
    const float* rl = r + (size_t)lang * RANKV * E_DIM;
    const float* sl = s + (size_t)lang * RANKV * N;
    int k0 = blockIdx.y * 32, n0 = blockIdx.x * 32;
    int tx = threadIdx.x, ty = threadIdx.y;        // 32 x 8
#pragma unroll
    for (int i = 0; i < 32; i += 8) {
        int k = k0 + ty + i, n = n0 + tx;
        float v = base[(size_t)k * N + n];
#pragma unroll
        for (int q = 0; q < RANKV; ++q)
            v += rl[q * E_DIM + k] * sl[(size_t)q * N + n];
        tile[ty + i][tx] = v;
    }
    __syncthreads();
#pragma unroll
    for (int i = 0; i < 32; i += 8) {
        int n = n0 + ty + i, k = k0 + tx;
        __nv_bfloat16 h, l; bsplit(tile[tx][ty + i], h, l);
        oh[(size_t)n * E_DIM + k] = h;
        ol[(size_t)n * E_DIM + k] = l;
    }
}

// ---- elementwise fp32 -> bf16 hi/lo split ----------------------------------
__global__ void split_kernel(const float* __restrict__ x,
                             __nv_bfloat16* __restrict__ h,
                             __nv_bfloat16* __restrict__ l)
{
    size_t i = ((size_t)blockIdx.x * blockDim.x + threadIdx.x) * 4;
    float4 v = *(const float4*)(x + i);
    float vv[4] = {v.x, v.y, v.z, v.w};
    __nv_bfloat16 hh[4], ll[4];
#pragma unroll
    for (int c = 0; c < 4; ++c) bsplit(vv[c], hh[c], ll[c]);
    *(__nv_bfloat162*)(h + i)     = {hh[0], hh[1]};
    *(__nv_bfloat162*)(h + i + 2) = {hh[2], hh[3]};
    *(__nv_bfloat162*)(l + i)     = {ll[0], ll[1]};
    *(__nv_bfloat162*)(l + i + 2) = {ll[2], ll[3]};
}

// ============================================================================
// Warp-MMA NT GEMM: C[M, 4*WN per CTA] = (Ah+Al)[M,K] @ (Bh+Bl)[N,K]^T
// (drops Al@Bl). CTA tile 128 x 4*WN, 8 warps (2 m x 4 n), warp tile 64 x WN,
// BK=32, cp.async double-buffered. Smem stride 40 halves (conflict-free).
// EPI: 0 = fp32 store + bias; 1 = fp32 store; 2 = Transformer-XL rel-shift
// scatter-add [verified bijection]; 3 = ctx bf16 hi/lo split store.
// ============================================================================
template<int WN, int EPI>
__global__ __launch_bounds__(256, 1)
void gemm_mma(const __nv_bfloat16* __restrict__ Ah, const __nv_bfloat16* __restrict__ Al,
              const __nv_bfloat16* __restrict__ Bh, const __nv_bfloat16* __restrict__ Bl,
              const float* __restrict__ bias, float* __restrict__ Cf,
              __nv_bfloat16* __restrict__ Ch, __nv_bfloat16* __restrict__ Cl,
              int K, int ldc, long sAz, long sBz, long sCz, int bmod)
{
    constexpr int NT    = WN / 8;
    constexpr int NROWS = 4 * WN;
    constexpr int ALOFF = 5120;                  // 128 * 40 halves
    constexpr int BHOFF = 10240;
    constexpr int BLOFF = BHOFF + NROWS * 40;
    constexpr int BUFH  = BHOFF + 2 * NROWS * 40;

    extern __shared__ __nv_bfloat16 smem[];
    uint32_t sb = smem_to_u32(smem);
    int tid = threadIdx.x, lid = tid & 31, wid = tid >> 5;
    int g = lid >> 2, t4 = lid & 3;
    int warpM = wid & 1, warpN = wid >> 1;
    int z = blockIdx.z;
    int zb = bmod ? (z % bmod) : z;
    Ah += (size_t)z * sAz;  Al += (size_t)z * sAz;
    Bh += (size_t)zb * sBz; Bl += (size_t)zb * sBz;
    if (EPI != 3) Cf += (size_t)z * sCz;
    int m0 = blockIdx.y * 128, n0 = blockIdx.x * (4 * WN);

    float acc[4][NT][4];
#pragma unroll
    for (int a = 0; a < 4; ++a)
#pragma unroll
        for (int b = 0; b < NT; ++b)
#pragma unroll
            for (int c = 0; c < 4; ++c) acc[a][b][c] = 0.f;

    const int NC = K >> 5;

    auto load_chunk = [&](int ch, int buf) {
        int k0 = ch << 5;
        uint32_t base = sb + (uint32_t)buf * (BUFH * 2);
#pragma unroll
        for (int idx = tid; idx < 1024; idx += 256) {          // A: 128r x 4c x 2 splits
            int split = idx >> 9, rc = idx & 511;
            int r = rc >> 2, c8 = rc & 3;
            const __nv_bfloat16* src = (split ? Al : Ah) + (size_t)(m0 + r) * K + k0 + c8 * 8;
            uint32_t dst = base + ((split ? ALOFF : 0) + r * 40 + c8 * 8) * 2;
            CP_ASYNC16(dst, src);
        }
#pragma unroll
        for (int idx = tid; idx < NROWS * 8; idx += 256) {     // B: NROWS x 4c x 2 splits
            int split = (idx >= NROWS * 4) ? 1 : 0;
            int o = split ? idx - NROWS * 4 : idx;
            int r = o >> 2, c8 = o & 3;
            const __nv_bfloat16* src = (split ? Bl : Bh) + (size_t)(n0 + r) * K + k0 + c8 * 8;
            uint32_t dst = base + ((split ? BLOFF : BHOFF) + r * 40 + c8 * 8) * 2;
            CP_ASYNC16(dst, src);
        }
    };

    load_chunk(0, 0);
    CP_COMMIT();
    for (int ch = 0; ch < NC; ++ch) {
        int buf = ch & 1;
        if (ch + 1 < NC) { load_chunk(ch + 1, buf ^ 1); CP_COMMIT(); CP_WAIT1(); }
        else            { CP_WAIT0(); }
        __syncthreads();
        const __nv_bfloat16* Ab = smem + buf * BUFH;
#pragma unroll
        for (int kk = 0; kk < 32; kk += 16) {
            uint32_t af[4][2][4], bfr[NT][2][2];
#pragma unroll
            for (int mt = 0; mt < 4; ++mt) {
                const __nv_bfloat16* p = Ab + (warpM * 64 + mt * 16 + g) * 40 + kk + t4 * 2;
                af[mt][0][0] = *(const uint32_t*)p;
                af[mt][0][1] = *(const uint32_t*)(p + 320);    // row +8
                af[mt][0][2] = *(const uint32_t*)(p + 8);      // k  +8
                af[mt][0][3] = *(const uint32_t*)(p + 328);
                const __nv_bfloat16* q = p + ALOFF;
                af[mt][1][0] = *(const uint32_t*)q;
                af[mt][1][1] = *(const uint32_t*)(q + 320);
                af[mt][1][2] = *(const uint32_t*)(q + 8);
                af[mt][1][3] = *(const uint32_t*)(q + 328);
            }
#pragma unroll
            for (int nt = 0; nt < NT; ++nt) {
                const __nv_bfloat16* p = Ab + BHOFF + (warpN * WN + nt * 8 + g) * 40 + kk + t4 * 2;
                bfr[nt][0][0] = *(const uint32_t*)p;
                bfr[nt][0][1] = *(const uint32_t*)(p + 8);
                const __nv_bfloat16* q = p + NROWS * 40;
                bfr[nt][1][0] = *(const uint32_t*)q;
                bfr[nt][1][1] = *(const uint32_t*)(q + 8);
            }
#pragma unroll
            for (int mt = 0; mt < 4; ++mt)
#pragma unroll
                for (int nt = 0; nt < NT; ++nt) {
                    mma16816(acc[mt][nt], af[mt][0], bfr[nt][0]);   // Ah*Bh
                    mma16816(acc[mt][nt], af[mt][0], bfr[nt][1]);   // Ah*Bl
                    mma16816(acc[mt][nt], af[mt][1], bfr[nt][0]);   // Al*Bh
                }
        }
        __syncthreads();
    }

    // ---- epilogue ----
#pragma unroll
    for (int mt = 0; mt < 4; ++mt) {
        int mrow = m0 + warpM * 64 + mt * 16 + g;
#pragma unroll
        for (int nt = 0; nt < NT; ++nt) {
            float* c = acc[mt][nt];
            int col = n0 + warpN * WN + nt * 8 + t4 * 2;
            if (EPI == 0) {
                float b0 = bias[col], b1 = bias[col + 1];
                *(float2*)&Cf[(size_t)mrow * ldc + col]       = make_float2(c[0] + b0, c[1] + b1);
                *(float2*)&Cf[(size_t)(mrow + 8) * ldc + col] = make_float2(c[2] + b0, c[3] + b1);
            } else if (EPI == 1) {
                *(float2*)&Cf[(size_t)mrow * ldc + col]       = make_float2(c[0], c[1]);
                *(float2*)&Cf[(size_t)(mrow + 8) * ldc + col] = make_float2(c[2], c[3]);
            } else if (EPI == 2) {
                // raw bd (m,n): n>=1023-m -> C[m][n+m-1023] += v ; else if m>=1 -> C[m-1][n+m+1] += v
#pragma unroll
                for (int e = 0; e < 4; ++e) {
                    int m = mrow + (e >> 1) * 8;
                    int n = col + (e & 1);
                    float v = c[e];
                    int jj = n + m - 1023;
                    if (jj >= 0)      Cf[(size_t)m * 1024 + jj] += v;
                    else if (m >= 1)  Cf[(size_t)(m - 1) * 1024 + (n + m + 1)] += v;
                }
            } else {
                int colb = (z >> 4) * 1024 + (z & 15) * 64 + warpN * WN + nt * 8 + t4 * 2;
                __nv_bfloat16 h0, l0, h1, l1;
                bsplit(c[0], h0, l0); bsplit(c[1], h1, l1);
                *(__nv_bfloat162*)&Ch[(size_t)mrow * 4096 + colb] = {h0, h1};
                *(__nv_bfloat162*)&Cl[(size_t)mrow * 4096 + colb] = {l0, l1};
                bsplit(c[2], h0, l0); bsplit(c[3], h1, l1);
                *(__nv_bfloat162*)&Ch[(size_t)(mrow + 8) * 4096 + colb] = {h0, h1};
                *(__nv_bfloat162*)&Cl[(size_t)(mrow + 8) * 4096 + colb] = {l0, l1};
            }
        }
    }
}

// ---------------- scatter qkv -> head-major bf16 hi/lo (v transposed) -------
__global__ void scatter_qkv_split(const float* __restrict__ qkv,
                                  const float* __restrict__ rwb,
                                  const float* __restrict__ rrb,
                                  __nv_bfloat16* __restrict__ qwh, __nv_bfloat16* __restrict__ qwl,
                                  __nv_bfloat16* __restrict__ qrh, __nv_bfloat16* __restrict__ qrl,
                                  __nv_bfloat16* __restrict__ kh,  __nv_bfloat16* __restrict__ kl,
                                  __nv_bfloat16* __restrict__ vth, __nv_bfloat16* __restrict__ vtl)
{
    size_t i = (size_t)blockIdx.x * blockDim.x + threadIdx.x;
    int row = (int)(i / 3072);
    int col = (int)(i % 3072);
    int t = row >> 2, b = row & 3;
    int sec = col >> 10, f = col & 1023;
    int h = f >> 6, d = f & 63;
    int zz = b * 16 + h;
    size_t dst  = (((size_t)zz * 1024 + t) << 6) + d;        // [z][t][d]
    size_t dstv = (((size_t)zz * 64 + d) << 10) + t;         // [z][d][t]  (v^T)
    float v = qkv[i];
    __nv_bfloat16 hh, ll;
    if (sec == 0) {
        bsplit(v + rwb[f], hh, ll); qwh[dst] = hh; qwl[dst] = ll;
        bsplit(v + rrb[f], hh, ll); qrh[dst] = hh; qrl[dst] = ll;
    } else if (sec == 1) {
        bsplit(v, hh, ll); kh[dst] = hh; kl[dst] = ll;
    } else {
        bsplit(v, hh, ll); vth[dstv] = hh; vtl[dstv] = ll;
    }
}

// ---------------- scatter rk_tmp[T,E] -> rk[H,T,D] bf16 hi/lo ---------------
__global__ void scatter_rk_split(const float* __restrict__ tmp,
                                 __nv_bfloat16* __restrict__ rh,
                                 __nv_bfloat16* __restrict__ rl)
{
    size_t i = (size_t)blockIdx.x * blockDim.x + threadIdx.x;
    int j = (int)(i >> 10), f = (int)(i & 1023);
    int h = f >> 6, d = f & 63;
    size_t dst = (((size_t)h * 1024 + j) << 6) + d;
    __nv_bfloat16 hh, ll;
    bsplit(tmp[i], hh, ll);
    rh[dst] = hh; rl[dst] = ll;
}

// ---------------- rowwise softmax -> bf16 hi/lo attn ------------------------
__global__ __launch_bounds__(256)
void softmax_kernel(const float* __restrict__ scores,
                    const unsigned char* __restrict__ mask,
                    __nv_bfloat16* __restrict__ ah, __nv_bfloat16* __restrict__ al)
{
    int row = blockIdx.x;                  // z*1024 + i
    int b = row >> 14;
    const float* p = scores + (size_t)row * 1024;
    int t = threadIdx.x;
    int lane = t & 31, wid = t >> 5;
    float4 v = ((const float4*)p)[t];
    float x[4] = {v.x, v.y, v.z, v.w};
    const unsigned char* mb = mask + (size_t)b * 1024 + t * 4;
    const float scale = 0.125f;            // 1/sqrt(64)
#pragma unroll
    for (int c = 0; c < 4; ++c) {
        x[c] *= scale;
        if (mb[c]) x[c] = -1e9f;
    }
    __shared__ float wred[8];
    float mx = fmaxf(fmaxf(x[0], x[1]), fmaxf(x[2], x[3]));
#pragma unroll
    for (int off = 16; off > 0; off >>= 1)
        mx = fmaxf(mx, __shfl_xor_sync(0xFFFFFFFFu, mx, off));
    if (lane == 0) wred[wid] = mx;
    __syncthreads();
    float m0 = wred[0];
#pragma unroll
    for (int w = 1; w < 8; ++w) m0 = fmaxf(m0, wred[w]);
    float sum = 0.f;
#pragma unroll
    for (int c = 0; c < 4; ++c) { x[c] = __expf(x[c] - m0); sum += x[c]; }
#pragma unroll
    for (int off = 16; off > 0; off >>= 1)
        sum += __shfl_xor_sync(0xFFFFFFFFu, sum, off);
    __syncthreads();
    if (lane == 0) wred[wid] = sum;
    __syncthreads();
    float s0 = wred[0];
#pragma unroll
    for (int w = 1; w < 8; ++w) s0 += wred[w];
    float inv = 1.0f / s0;
    __nv_bfloat16 hh[4], ll[4];
#pragma unroll
    for (int c = 0; c < 4; ++c) bsplit(x[c] * inv, hh[c], ll[c]);
    size_t o = (size_t)row * 1024 + t * 4;
    *(__nv_bfloat162*)(ah + o)     = {hh[0], hh[1]};
    *(__nv_bfloat162*)(ah + o + 2) = {hh[2], hh[3]};
    *(__nv_bfloat162*)(al + o)     = {ll[0], ll[1]};
    *(__nv_bfloat162*)(al + o + 2) = {ll[2], ll[3]};
}

// ---------------------------------------------------------------------------
#define SMEM_W32 81920   // 2 * (10240 + 2*128*40) * 2 B
#define SMEM_W16 61440   // 2 * (10240 + 2*64*40) * 2 B

extern "C" void kernel_launch(void* const* d_in, const int* in_sizes, int n_in,
                              void* d_out, int out_size)
{
    const float* input  = (const float*)d_in[0];
    const float* pos    = (const float*)d_in[1];
    const int*   indices= (const int*)d_in[2];
    const unsigned char* mask = (const unsigned char*)d_in[3];
    const float* w_in_b = (const float*)d_in[4];
    const float* w_pos_b= (const float*)d_in[5];
    const float* w_out_b= (const float*)d_in[6];
    const float* b_in   = (const float*)d_in[7];
    const float* b_pos  = (const float*)d_in[8];
    const float* b_out  = (const float*)d_in[9];
    const float* r_i = (const float*)d_in[10];
    const float* s_i = (const float*)d_in[11];
    const float* r_p = (const float*)d_in[12];
    const float* s_p = (const float*)d_in[13];
    const float* r_o = (const float*)d_in[14];
    const float* s_o = (const float*)d_in[15];
    const float* r_w_bias = (const float*)d_in[16];
    const float* r_r_bias = (const float*)d_in[17];
    float* out = (float*)d_out;

    float *qkv, *rktmp, *scores;
    __nv_bfloat16 *qwh,*qwl,*qrh,*qrl,*kh,*kl,*vth,*vtl,*rkh,*rkl,*ath,*atl,*cxh,*cxl;
    __nv_bfloat16 *wtih,*wtil,*wtph,*wtpl,*wtoh,*wtol,*inh,*inl,*psh,*psl;
    cudaGetSymbolAddress((void**)&qkv,   g_qkv);
    cudaGetSymbolAddress((void**)&rktmp, g_rktmp);
    cudaGetSymbolAddress((void**)&scores,g_scores);
    cudaGetSymbolAddress((void**)&qwh, g_qwh); cudaGetSymbolAddress((void**)&qwl, g_qwl);
    cudaGetSymbolAddress((void**)&qrh, g_qrh); cudaGetSymbolAddress((void**)&qrl, g_qrl);
    cudaGetSymbolAddress((void**)&kh,  g_kh);  cudaGetSymbolAddress((void**)&kl,  g_kl);
    cudaGetSymbolAddress((void**)&vth, g_vth); cudaGetSymbolAddress((void**)&vtl, g_vtl);
    cudaGetSymbolAddress((void**)&rkh, g_rkh); cudaGetSymbolAddress((void**)&rkl, g_rkl);
    cudaGetSymbolAddress((void**)&ath, g_ath); cudaGetSymbolAddress((void**)&atl, g_atl);
    cudaGetSymbolAddress((void**)&cxh, g_cxh); cudaGetSymbolAddress((void**)&cxl, g_cxl);
    cudaGetSymbolAddress((void**)&wtih,g_wtih);cudaGetSymbolAddress((void**)&wtil,g_wtil);
    cudaGetSymbolAddress((void**)&wtph,g_wtph);cudaGetSymbolAddress((void**)&wtpl,g_wtpl);
    cudaGetSymbolAddress((void**)&wtoh,g_wtoh);cudaGetSymbolAddress((void**)&wtol,g_wtol);
    cudaGetSymbolAddress((void**)&inh, g_inh); cudaGetSymbolAddress((void**)&inl, g_inl);
    cudaGetSymbolAddress((void**)&psh, g_psh); cudaGetSymbolAddress((void**)&psl, g_psl);

    cudaFuncSetAttribute(gemm_mma<32,0>, cudaFuncAttributeMaxDynamicSharedMemorySize, SMEM_W32);
    cudaFuncSetAttribute(gemm_mma<32,1>, cudaFuncAttributeMaxDynamicSharedMemorySize, SMEM_W32);
    cudaFuncSetAttribute(gemm_mma<32,2>, cudaFuncAttributeMaxDynamicSharedMemorySize, SMEM_W32);
    cudaFuncSetAttribute(gemm_mma<16,3>, cudaFuncAttributeMaxDynamicSharedMemorySize, SMEM_W16);

    // 1) weights: W^T + low-rank, bf16 hi/lo; activation splits
    build_wt_split<<<dim3(3072 / 32, 1024 / 32), dim3(32, 8)>>>(w_in_b,  r_i, s_i, indices, wtih, wtil, 3072);
    build_wt_split<<<dim3(1024 / 32, 1024 / 32), dim3(32, 8)>>>(w_pos_b, r_p, s_p, indices, wtph, wtpl, 1024);
    build_wt_split<<<dim3(1024 / 32, 1024 / 32), dim3(32, 8)>>>(w_out_b, r_o, s_o, indices, wtoh, wtol, 1024);
    split_kernel<<<4096, 256>>>(input, inh, inl);
    split_kernel<<<1024, 256>>>(pos, psh, psl);

    // 2) qkv = input @ w_in + b_in     [4096,1024] x [3072,1024]^T
    gemm_mma<32,0><<<dim3(24, 32, 1), 256, SMEM_W32>>>(
        inh, inl, wtih, wtil, b_in, qkv, nullptr, nullptr, 1024, 3072, 0, 0, 0, 0);

    // 3) scatter + split to head-major bf16 (v transposed)
    scatter_qkv_split<<<49152, 256>>>(qkv, r_w_bias, r_r_bias, qwh, qwl, qrh, qrl, kh, kl, vth, vtl);

    // 4) r_head_k = pos @ w_pos + b_pos, then split-scatter
    gemm_mma<32,0><<<dim3(8, 8, 1), 256, SMEM_W32>>>(
        psh, psl, wtph, wtpl, b_pos, rktmp, nullptr, nullptr, 1024, 1024, 0, 0, 0, 0);
    scatter_rk_split<<<4096, 256>>>(rktmp, rkh, rkl);

    // 5) ac scores (plain store), per z = b*16+h
    gemm_mma<32,1><<<dim3(8, 8, 64), 256, SMEM_W32>>>(
        qwh, qwl, kh, kl, nullptr, scores, nullptr, nullptr,
        64, 1024, 65536, 65536, 1048576, 0);

    // 6) bd scores (rel-shift scatter-add); rk shared across batch (bmod=16)
    gemm_mma<32,2><<<dim3(8, 8, 64), 256, SMEM_W32>>>(
        qrh, qrl, rkh, rkl, nullptr, scores, nullptr, nullptr,
        64, 1024, 65536, 65536, 1048576, 16);

    // 7) softmax -> bf16 hi/lo attn
    softmax_kernel<<<65536, 256>>>(scores, mask, ath, atl);

    // 8) ctx = attn @ vT^T per z -> bf16 hi/lo into [T, B*E] interleave
    gemm_mma<16,3><<<dim3(1, 8, 64), 256, SMEM_W16>>>(
        ath, atl, vth, vtl, nullptr, nullptr, cxh, cxl,
        1024, 4096, 1048576, 65536, 0, 0);

    // 9) out = ctx @ w_out + b_out
    gemm_mma<32,0><<<dim3(8, 32, 1), 256, SMEM_W32>>>(
        cxh, cxl, wtoh, wtol, b_out, out, nullptr, nullptr, 1024, 1024, 0, 0, 0, 0);
}